// round 17
// baseline (speedup 1.0000x reference)
#include <cuda_runtime.h>
#include <cuda_fp16.h>

// LinearInterpolator: B=8, grid 64^3 fp32, M=96^3 query points, trilinear.
// inputs: d_in[0]=y (8*64^3 fp32), d_in[1]=xnew (8*M*3 fp32)
// output: d_out = 8*M fp32
//
// fp16 8-corner pack (16B/cell, 32 MB) + single LDG.128 gather per point,
// with an L2 evict-last cache-hint policy on the gather so the pack stays
// L2-resident against the streamed (.cs) xnew/out traffic. Prepack:
// quarter-plane smem tiles, 2048 blocks.

static constexpr int B_ = 8;
static constexpr int D_ = 64;
static constexpr int GRID3 = D_ * D_ * D_;        // 262144 = 2^18
static constexpr int M_ = 96 * 96 * 96;           // 884736
static constexpr int PPT = 4;                     // points per thread (interp)

// cell layout (16B): h2{c000,c001} h2{c010,c011} h2{c100,c101} h2{c110,c111}
__device__ uint4 g_pack[B_ * GRID3];              // 32 MB static scratch

__device__ __forceinline__ unsigned pack2(float a, float b)
{
    __half2 h = __floats2half2_rn(a, b);
    return *reinterpret_cast<unsigned*>(&h);
}

// evict-last policy register (fractional form, 100% evict_last)
__device__ __forceinline__ unsigned long long mk_policy_el()
{
    unsigned long long pol;
    asm("createpolicy.fractional.L2::evict_last.b64 %0, 1.0;" : "=l"(pol));
    return pol;
}

// gather with L2 cache-hint (evict-last) -- legal 16B form on sm_103
__device__ __forceinline__ uint4 ldg_el(const uint4* p, unsigned long long pol)
{
    uint4 v;
    asm volatile("ld.global.nc.L2::cache_hint.v4.u32 {%0,%1,%2,%3}, [%4], %5;"
                 : "=r"(v.x), "=r"(v.y), "=r"(v.z), "=r"(v.w)
                 : "l"(p), "l"(pol));
    return v;
}

// One block per (batch, i0, i1-quarter). smem: 17 rows x 64 cols per plane
// (row 16 is the clamped i1+1 boundary row). 2048 blocks total.
static constexpr int QROWS = 17;

__global__ __launch_bounds__(256)
void prepack_kernel(const float* __restrict__ y)
{
    __shared__ float P0[QROWS * D_];              // 4.25 KB
    __shared__ float P1[QROWS * D_];              // 4.25 KB

    const int quarter = blockIdx.x & 3;
    const int i0      = (blockIdx.x >> 2) & 63;
    const int b       = blockIdx.x >> 8;
    const int i0p     = min(i0 + 1, D_ - 1);
    const int i1q     = quarter << 4;             // 0,16,32,48
    const int tid     = threadIdx.x;

    const float* __restrict__ pl0 = y + ((size_t)b << 18) + (i0  << 12);
    const float* __restrict__ pl1 = y + ((size_t)b << 18) + (i0p << 12);

    // load 17 rows x 16 float4 = 272 float4 per plane (rows clamped at 63)
    float4* s0 = reinterpret_cast<float4*>(P0);
    float4* s1 = reinterpret_cast<float4*>(P1);
#pragma unroll
    for (int k = 0; k < 2; k++) {
        int v = tid + 256 * k;                    // float4 index within tile
        if (v < QROWS * 16) {
            int r = v >> 4;                       // local row 0..16
            int c = v & 15;                       // float4 col
            int g = min(i1q + r, D_ - 1);         // clamped global i1
            s0[v] = reinterpret_cast<const float4*>(pl0 + (g << 6))[c];
            s1[v] = reinterpret_cast<const float4*>(pl1 + (g << 6))[c];
        }
    }
    __syncthreads();

    const int i2  = tid & 63;
    const int i2p = min(i2 + 1, D_ - 1);
    const int jb  = (tid >> 6) << 2;              // local row base: 0,4,8,12

    uint4* __restrict__ dst = g_pack + ((size_t)b << 18) + (i0 << 12)
                            + ((i1q + jb) << 6) + i2;

    float a0 = P0[(jb << 6) + i2],  a1 = P0[(jb << 6) + i2p];
    float e0 = P1[(jb << 6) + i2],  e1 = P1[(jb << 6) + i2p];

#pragma unroll
    for (int j = 0; j < 4; j++) {
        const int rn = jb + j + 1;                // <= 16, in-tile (pre-clamped)
        const float c0 = P0[(rn << 6) + i2], c1 = P0[(rn << 6) + i2p];
        const float d0 = P1[(rn << 6) + i2], d1 = P1[(rn << 6) + i2p];

        uint4 cc;
        cc.x = pack2(a0, a1);     // c000, c001
        cc.y = pack2(c0, c1);     // c010, c011
        cc.z = pack2(e0, e1);     // c100, c101
        cc.w = pack2(d0, d1);     // c110, c111
        dst[j << 6] = cc;

        a0 = c0; a1 = c1; e0 = d0; e1 = d1;
    }
}

// Interp: R8/R14 configuration (measured floor for this gather structure).
__global__ __launch_bounds__(256)
void interp_kernel(const float* __restrict__ xnew,
                   float* __restrict__ out)
{
    const int t = blockIdx.x * blockDim.x + threadIdx.x;
    const int totalT = (B_ * M_) / PPT;
    if (t >= totalT) return;

    const int p0 = t * PPT;
    const int b  = p0 / M_;                       // M_ % 4 == 0: same batch
    const uint4* __restrict__ cp = g_pack + ((size_t)b << 18);

    const unsigned long long pol = mk_policy_el();

    const float4* __restrict__ xv = reinterpret_cast<const float4*>(xnew) + (size_t)t * 3;
    float4 v0 = __ldcs(xv + 0);
    float4 v1 = __ldcs(xv + 1);
    float4 v2 = __ldcs(xv + 2);

    float cx[PPT] = { v0.x, v0.w, v1.z, v2.y };
    float cy[PPT] = { v0.y, v1.x, v1.w, v2.z };
    float cz[PPT] = { v0.z, v1.y, v2.x, v2.w };

    uint4 cc[PPT];
    float o0[PPT], o1[PPT], o2[PPT];
#pragma unroll
    for (int i = 0; i < PPT; i++) {
        float r0 = cx[i] * 63.0f;
        float r1 = cy[i] * 63.0f;
        float r2 = cz[i] * 63.0f;
        float f0 = floorf(r0), f1 = floorf(r1), f2 = floorf(r2);
        o0[i] = r0 - f0; o1[i] = r1 - f1; o2[i] = r2 - f2;
        int base = ((int)f0 << 12) | ((int)f1 << 6) | (int)f2;
        cc[i] = ldg_el(cp + base, pol);
    }

    float4 res;
    float* resp = reinterpret_cast<float*>(&res);
#pragma unroll
    for (int i = 0; i < PPT; i++) {
        float2 f00 = __half22float2(*reinterpret_cast<__half2*>(&cc[i].x)); // c000,c001
        float2 f01 = __half22float2(*reinterpret_cast<__half2*>(&cc[i].y)); // c010,c011
        float2 f10 = __half22float2(*reinterpret_cast<__half2*>(&cc[i].z)); // c100,c101
        float2 f11 = __half22float2(*reinterpret_cast<__half2*>(&cc[i].w)); // c110,c111

        float a00 = f00.x + (f10.x - f00.x) * o0[i];
        float a01 = f00.y + (f10.y - f00.y) * o0[i];
        float a10 = f01.x + (f11.x - f01.x) * o0[i];
        float a11 = f01.y + (f11.y - f01.y) * o0[i];

        float b0 = a00 + (a10 - a00) * o1[i];
        float b1 = a01 + (a11 - a01) * o1[i];
        resp[i] = b0 + (b1 - b0) * o2[i];
    }

    __stcs(reinterpret_cast<float4*>(out) + t, res);
}

extern "C" void kernel_launch(void* const* d_in, const int* in_sizes, int n_in,
                              void* d_out, int out_size)
{
    const float* y    = (const float*)d_in[0];
    const float* xnew = (const float*)d_in[1];
    float* out        = (float*)d_out;

    prepack_kernel<<<B_ * D_ * 4, 256>>>(y);      // 2048 blocks

    const int totalT = (B_ * M_) / PPT;           // 1,769,472
    interp_kernel<<<totalT / 256, 256>>>(xnew, out);   // 6912 blocks
}